// round 17
// baseline (speedup 1.0000x reference)
#include <cuda_runtime.h>
#include <math.h>

// ---------------- problem constants ----------------
#define BB     16
#define F1N    16
#define CC     64
#define TTOT   1000
#define KK     64
#define C2N    32
#define PWN    16
#define EPSF   1e-5f

// ---------------- kernel-1 tiling ----------------
#define TILE   112         // time points per block
#define NTILE  9           // 9*112 = 1008 >= 1000 (last tile partial)
#define TSUB   16          // chunk of t per phase round
#define NCHUNK 7           // 7*16 = 112
#define XS_W   181         // staged from t0-32; odd -> conflict-free
#define XS_NV  45          // float4 loads per row (180 floats)
#define ES_S   17          // es row stride (odd -> conflict-free)

// smem float counts
#define NF_XS   (CC*XS_W)       // 11584
#define NF_WS   (F1N*KK)        // 1024
#define NF_AH   (CC*CC)         // 4096 (reused as xg/ps double buffers)
#define NF_DW   (C2N*CC)        // 2048
#define NF_ES1  (F1N*CC*ES_S)   // 17408 (one buffer)
#define NF_M0   (C2N*CC)        // 2048
#define NF_SMALL 144
#define SMEM_FLOATS (NF_XS+NF_WS+NF_AH+NF_DW+2*NF_ES1+NF_M0+NF_SMALL)
#define SMEM_BYTES  (SMEM_FLOATS*4)   // ~223 KB <= 232448 cap

// K2 tiling
#define K2B_W    8
#define K2B_T    (K2B_W*PWN)  // 128
#define NTILE2   8
#define NPOOL    62

__device__ float g_h2[BB * C2N * TTOT];
__device__ float g_psum[BB * C2N * NTILE];
__device__ float g_pmax[BB * C2N * NTILE];
__device__ float g_q[BB * C2N * NPOOL];
__device__ int   g_cnt[BB];          // zero-init; tail block resets each run

__device__ __forceinline__ float eluf(float v) {
    return v > 0.f ? v : (__expf(v) - 1.f);   // MUFU exp; err ~2e-7
}

#define BAR_SYNC(id, cnt)   asm volatile("bar.sync %0, %1;"   :: "r"(id), "r"(cnt) : "memory")
#define BAR_ARRIVE(id, cnt) asm volatile("bar.arrive %0, %1;" :: "r"(id), "r"(cnt) : "memory")

// ============================================================
// Kernel 1: warp-specialized producer/consumer, split prologue.
// grid (NTILE, BB) = 144 blocks, 1024 threads
// ============================================================
__global__ void __launch_bounds__(1024, 1)
k1_front(const float* __restrict__ x,
         const float* __restrict__ ahat_g,
         const float* __restrict__ w1,  const float* __restrict__ b1c,
         const float* __restrict__ g1,  const float* __restrict__ bb1,
         const float* __restrict__ m1,  const float* __restrict__ v1,
         const float* __restrict__ gcw, const float* __restrict__ gcb,
         const float* __restrict__ dww_g, const float* __restrict__ dwb,
         const float* __restrict__ g2,  const float* __restrict__ bb2,
         const float* __restrict__ m2,  const float* __restrict__ v2)
{
    extern __shared__ float sm[];
    float* xs  = sm;                 // [CC][XS_W] (x[t0-32+j])
    float* ws  = xs  + NF_XS;        // [F1][KK] (BN1-scaled weights)
    float* ah  = ws  + NF_WS;        // [CC][CC]; later xg/ps parity buffers
    float* dw  = ah  + NF_AH;        // [C2][CC] (16B aligned)
    float* es0 = dw  + NF_DW;        // [F1][CC][ES_S] buffer 0
    float* es1 = es0 + NF_ES1;       // buffer 1
    float* m0  = es1 + NF_ES1;       // [C2][CC] (16B aligned)
    float* o1s = m0  + NF_M0;        // [F1]
    float* s2  = o1s + F1N + F1N;    // [C2]
    float* sh2 = s2  + C2N;          // [C2]
    float* cst = sh2 + C2N;          // [C2]

    const int tid = threadIdx.x;
    const int b   = blockIdx.y;
    const int t0  = blockIdx.x * TILE;

    if (tid < 512) {
        // ================= CONV PRODUCER (warps 0-15) =================
        // xs staged from t0-32 (4-aligned) via float4
        for (int iv = tid; iv < CC * XS_NV; iv += 512) {
            int c = iv / XS_NV, q = iv % XS_NV;
            int tg = t0 - 32 + 4 * q;
            const float* xr = x + (b * CC + c) * TTOT;
            float4 v;
            if (tg >= 0 && tg + 3 < TTOT) {
                v = *(const float4*)(xr + tg);
            } else {
                v.x = (tg + 0 >= 0 && tg + 0 < TTOT) ? xr[tg + 0] : 0.f;
                v.y = (tg + 1 >= 0 && tg + 1 < TTOT) ? xr[tg + 1] : 0.f;
                v.z = (tg + 2 >= 0 && tg + 2 < TTOT) ? xr[tg + 2] : 0.f;
                v.w = (tg + 3 >= 0 && tg + 3 < TTOT) ? xr[tg + 3] : 0.f;
            }
            float* d = xs + c * XS_W + 4 * q;
            d[0] = v.x; d[1] = v.y; d[2] = v.z; d[3] = v.w;
        }
        for (int i = tid; i < NF_WS; i += 512) {
            int f = i / KK;
            float s1 = g1[f] * rsqrtf(v1[f] + EPSF);
            ws[i] = w1[i] * s1;
        }
        if (tid < F1N) {
            float s1 = g1[tid] * rsqrtf(v1[tid] + EPSF);
            o1s[tid] = b1c[tid] * s1 + bb1[tid] - m1[tid] * s1;
        }
        BAR_SYNC(1, 512);            // producer staging complete

        const int fpair = tid >> 6;  // 0..7; computes filters fpair, fpair+8
        const int c     = tid & 63;
        const float* xrow = xs + c * XS_W + 1;   // +1: stage base is t0-32
        const float* wr0 = ws + fpair * KK;
        const float* wr1 = ws + (fpair + 8) * KK;
        const float o0 = o1s[fpair], o1v = o1s[fpair + 8];

        for (int chk = 0; chk < NCHUNK; ++chk) {
            const int p  = chk & 1;
            const int ct = chk * TSUB;
            float* esb = p ? es1 : es0;
            if (chk >= 2) BAR_SYNC(4 + p, 1024);   // wait es[p] consumed

            float acc0[TSUB], acc1[TSUB], win[TSUB];
            #pragma unroll
            for (int i = 0; i < TSUB; ++i) {
                acc0[i] = acc1[i] = 0.f;
                win[i] = xrow[ct + i];
            }
            int k = 0;
            #pragma unroll 1
            for (int m = 0; m < 4; ++m) {
                #pragma unroll
                for (int kk = 0; kk < 16; ++kk) {
                    float w0 = wr0[k + kk], w1v = wr1[k + kk];
                    #pragma unroll
                    for (int i = 0; i < TSUB; ++i) {
                        float xv = win[(kk + i) & 15];
                        acc0[i] = fmaf(w0, xv, acc0[i]);
                        acc1[i] = fmaf(w1v, xv, acc1[i]);
                    }
                    win[kk] = xrow[ct + k + kk + TSUB];
                }
                k += 16;
            }
            float* e0 = esb + (fpair * CC + c) * ES_S;
            float* e1 = esb + ((fpair + 8) * CC + c) * ES_S;
            #pragma unroll
            for (int i = 0; i < TSUB; ++i) {
                e0[i] = eluf(acc0[i] + o0);
                e1[i] = eluf(acc1[i] + o1v);
            }
            __threadfence_block();
            BAR_ARRIVE(2 + p, 1024);               // signal es[p] full
        }
    } else {
        // ================= PHASE CONSUMER (warps 16-31) =================
        const int tl  = tid - 512;        // 0..511
        const int c2  = tl >> 4;
        const int tt  = tl & 15;
        const int ff  = c2 >> 1;

        for (int i = tl; i < NF_AH; i += 512) ah[i] = ahat_g[i];
        for (int i = tl; i < NF_DW; i += 512) dw[i] = dww_g[i];
        if (tl < C2N) {
            float s = g2[tl] * rsqrtf(v2[tl] + EPSF);
            s2[tl]  = s;
            sh2[tl] = bb2[tl] - m2[tl] * s;
        }
        BAR_SYNC(7, 512);            // ah/dw loaded
        if (tl < C2N) {
            float wsum = 0.f;
            for (int c = 0; c < CC; ++c) wsum += dw[tl * CC + c];
            cst[tl] = gcb[tl >> 1] * wsum + dwb[tl];
        }
        for (int it = tl; it < C2N * CC; it += 512) {
            int cq = it >> 6, j = it & 63;
            const float* dr = dw + cq * CC;
            float s = 0.f;
            #pragma unroll 8
            for (int cc = 0; cc < CC; ++cc)
                s = fmaf(dr[cc], ah[cc * CC + j], s);
            m0[it] = s * gcw[cq >> 1] * (1.f / F1N);
        }
        BAR_SYNC(7, 512);            // M0 done; ah region now reusable

        float stat_s = 0.f, stat_m = -INFINITY;

        for (int chk = 0; chk < NCHUNK; ++chk) {
            const int p = chk & 1;
            const float* esb = p ? es1 : es0;
            float* xgb = ah + p * 2048;            // [CC*TSUB] = 1024
            float* psb = xgb + 1024;               // [C2*TSUB] = 512
            BAR_SYNC(2 + p, 1024);                 // wait es[p] full

            #pragma unroll
            for (int r = 0; r < 2; ++r) {
                int item = tl + r * 512;
                int cc = item >> 4, tti = item & 15;
                const float* er = esb + cc * ES_S + tti;
                float s = 0.f;
                #pragma unroll
                for (int f2 = 0; f2 < F1N; ++f2)
                    s += er[f2 * CC * ES_S];
                xgb[item] = s;                     // raw sum (M0 holds /F1)
            }
            {
                const float4* dr4 = (const float4*)(dw + c2 * CC);
                const float* er = esb + ff * CC * ES_S + tt;
                float s = 0.f;
                #pragma unroll
                for (int q = 0; q < 16; ++q) {
                    float4 d = dr4[q];
                    int cc = q * 4;
                    s = fmaf(d.x, er[(cc + 0) * ES_S], s);
                    s = fmaf(d.y, er[(cc + 1) * ES_S], s);
                    s = fmaf(d.z, er[(cc + 2) * ES_S], s);
                    s = fmaf(d.w, er[(cc + 3) * ES_S], s);
                }
                psb[tl] = s;
            }
            BAR_SYNC(6, 512);                      // es reads + xg writes done
            BAR_ARRIVE(4 + p, 1024);               // conv may overwrite es[p]

            {
                const float4* mr4 = (const float4*)(m0 + c2 * CC);
                const float* xr = xgb + tt;
                float s = psb[tl];
                #pragma unroll
                for (int q = 0; q < 16; ++q) {
                    float4 m = mr4[q];
                    int j = q * 4;
                    s = fmaf(m.x, xr[(j + 0) * TSUB], s);
                    s = fmaf(m.y, xr[(j + 1) * TSUB], s);
                    s = fmaf(m.z, xr[(j + 2) * TSUB], s);
                    s = fmaf(m.w, xr[(j + 3) * TSUB], s);
                }
                float outv = (s + cst[c2]) * s2[c2] + sh2[c2];
                int t = t0 + chk * TSUB + tt;
                bool valid = (t < TTOT);
                if (valid) g_h2[(b * C2N + c2) * TTOT + t] = outv;
                float sv = valid ? outv : 0.f;
                float mv = valid ? outv : -INFINITY;
                #pragma unroll
                for (int o = 8; o > 0; o >>= 1) {
                    sv += __shfl_down_sync(0xffffffffu, sv, o, 16);
                    mv  = fmaxf(mv, __shfl_down_sync(0xffffffffu, mv, o, 16));
                }
                if (tt == 0) { stat_s += sv; stat_m = fmaxf(stat_m, mv); }
            }
        }

        if (tt == 0) {
            g_psum[(b * C2N + c2) * NTILE + blockIdx.x] = stat_s;
            g_pmax[(b * C2N + c2) * NTILE + blockIdx.x] = stat_m;
        }
    }
}

// ============================================================
// Kernel 2: blocks 0-7 per batch: attn+pool -> g_q (+count);
//           block 8 per batch: spin, then sep-conv tail -> out.
// grid (NTILE2+1, BB), 256 threads
// ============================================================
#define H2S_S 131
__global__ void __launch_bounds__(256, 4)
k2_fused(const float* __restrict__ caw1, const float* __restrict__ cab1,
         const float* __restrict__ caw2, const float* __restrict__ cab2,
         const float* __restrict__ saw,
         const float* __restrict__ sag, const float* __restrict__ sab,
         const float* __restrict__ sam, const float* __restrict__ sav,
         const float* __restrict__ sepw, const float* __restrict__ sepb,
         const float* __restrict__ g3, const float* __restrict__ bb3,
         const float* __restrict__ m3, const float* __restrict__ v3,
         float* __restrict__ out)
{
    __shared__ float att[C2N];
    __shared__ float h2s[C2N * H2S_S];
    __shared__ float mms[K2B_T + 2], mxs[K2B_T + 2], sgs[K2B_T];
    __shared__ float sstat[C2N];

    const int tile = blockIdx.x, b = blockIdx.y;
    const int tid  = threadIdx.x;

    if (tile == NTILE2) {
        // ---------- tail block: wait for 8 siblings, then sep conv ----------
        if (tid == 0) {
            while (atomicAdd(&g_cnt[b], 0) < NTILE2) { }
        }
        __syncthreads();
        __threadfence();   // acquire: g_q writes visible

        float* qs = h2s;                     // 1984 floats
        float* swp = h2s + C2N * NPOOL;      // 512 floats
        for (int i = tid; i < C2N * NPOOL; i += 256)
            qs[i] = g_q[b * C2N * NPOOL + i];
        for (int i = tid; i < C2N * PWN; i += 256)
            swp[i] = sepw[i];
        __syncthreads();

        const int j  = tid & 15;
        const int e0 = tid >> 4;
        for (int r = 0; r < 6; ++r) {
            int e  = e0 + r * 16;            // 0..95 = c2*3 + to
            int c2 = e / 3, to = e % 3;
            int t  = to * PWN + j;
            float y = sepb[c2];
            #pragma unroll
            for (int u = 0; u < PWN; ++u) {
                int tq = t - 7 + u;
                if (tq >= 0 && tq < NPOOL)
                    y = fmaf(swp[c2 * PWN + u], qs[c2 * NPOOL + tq], y);
            }
            float s3  = g3[c2] * rsqrtf(v3[c2] + EPSF);
            float sh3 = bb3[c2] - m3[c2] * s3;
            float yb = y * s3 + sh3;
            float v = yb > 0.f ? yb : expm1f(yb);
            #pragma unroll
            for (int o = 8; o > 0; o >>= 1)
                v += __shfl_down_sync(0xffffffffu, v, o, 16);
            if (j == 0) out[b * (C2N * 3) + e] = v * (1.f / PWN);
        }
        __syncthreads();
        if (tid == 0) atomicExch(&g_cnt[b], 0);   // reset for graph replay
        return;
    }

    // ---------- k2b body (tiles 0-7) ----------
    const int t0 = tile * K2B_T;
    const int tw = (tile == NTILE2 - 1) ? (NPOOL * PWN - t0) : K2B_T;
    const int nw = tw / PWN;
    const int nv = tw >> 2;

    if (tid < C2N) {
        float s = 0.f, m = -INFINITY;
        const float* pss = g_psum + (b * C2N + tid) * NTILE;
        const float* pm = g_pmax + (b * C2N + tid) * NTILE;
        #pragma unroll
        for (int tl = 0; tl < NTILE; ++tl) {
            s += pss[tl]; m = fmaxf(m, pm[tl]);
        }
        sstat[tid] = s * (1.f / TTOT) + m;
    }
    __syncthreads();
    if (tid < C2N) {
        float r0 = cab1[0], r1 = cab1[1];
        for (int j = 0; j < C2N; ++j) {
            r0 += caw1[j] * sstat[j];
            r1 += caw1[C2N + j] * sstat[j];
        }
        r0 = fmaxf(r0, 0.f); r1 = fmaxf(r1, 0.f);
        float z = cab2[tid] + caw2[tid * 2] * r0 + caw2[tid * 2 + 1] * r1;
        att[tid] = 1.f / (1.f + expf(-z));
    }
    __syncthreads();

    const float* h2 = g_h2 + b * C2N * TTOT;
    for (int it = tid; it < C2N * nv; it += 256) {
        int c2 = it / nv, jj = it % nv;
        float4 v = *(const float4*)(h2 + c2 * TTOT + t0 + 4 * jj);
        float a = att[c2];
        float* d = h2s + c2 * H2S_S + 1 + 4 * jj;
        d[0] = v.x * a; d[1] = v.y * a; d[2] = v.z * a; d[3] = v.w * a;
    }
    if (tid < 64) {
        int c2 = tid >> 1, side = tid & 1;
        int t = side ? (t0 + tw) : (t0 - 1);
        float v = (t >= 0 && t < TTOT) ? h2[c2 * TTOT + t] * att[c2] : 0.f;
        h2s[c2 * H2S_S + (side ? tw + 1 : 0)] = v;
    }
    __syncthreads();

    for (int j = tid; j < tw + 2; j += 256) {
        float s = 0.f, mx = -INFINITY;
        #pragma unroll 8
        for (int c2 = 0; c2 < C2N; ++c2) {
            float v = h2s[c2 * H2S_S + j];
            s += v; mx = fmaxf(mx, v);
        }
        mms[j] = s * (1.f / C2N);
        mxs[j] = mx;
    }
    __syncthreads();

    {
        float ssa = sag[0] * rsqrtf(sav[0] + EPSF);
        float sha = sab[0] - sam[0] * ssa;
        for (int j = tid; j < tw; j += 256) {
            int t = t0 + j;
            float acc = 0.f;
            #pragma unroll
            for (int kw = 0; kw < 3; ++kw) {
                int tt = t - 1 + kw;
                if (tt >= 0 && tt < TTOT)
                    acc += saw[3 + kw] * mms[j + kw] + saw[12 + kw] * mxs[j + kw];
            }
            float z = acc * ssa + sha;
            sgs[j] = 1.f / (1.f + expf(-z));
        }
    }
    __syncthreads();

    {
        int c2 = tid & 31, w = tid >> 5;
        if (w < nw) {
            float acc = 0.f;
            #pragma unroll
            for (int j = 0; j < PWN; ++j) {
                int tl = w * PWN + j;
                float v = h2s[c2 * H2S_S + tl + 1] * sgs[tl];
                acc += (v > 0.f ? v : expm1f(v));
            }
            g_q[(b * C2N + c2) * NPOOL + tile * K2B_W + w] = acc * (1.f / PWN);
        }
    }

    __threadfence();                      // release g_q writes
    __syncthreads();
    if (tid == 0) atomicAdd(&g_cnt[b], 1);
}

// ============================================================
extern "C" void kernel_launch(void* const* d_in, const int* in_sizes, int n_in,
                              void* d_out, int out_size)
{
    const float* x     = (const float*)d_in[0];
    const float* ahat  = (const float*)d_in[1];
    const float* w1    = (const float*)d_in[2];
    const float* b1c   = (const float*)d_in[3];
    const float* g1    = (const float*)d_in[4];
    const float* bb1   = (const float*)d_in[5];
    const float* m1    = (const float*)d_in[6];
    const float* v1    = (const float*)d_in[7];
    const float* gcw   = (const float*)d_in[8];
    const float* gcb   = (const float*)d_in[9];
    const float* dww   = (const float*)d_in[10];
    const float* dwb   = (const float*)d_in[11];
    const float* g2    = (const float*)d_in[12];
    const float* bb2   = (const float*)d_in[13];
    const float* m2    = (const float*)d_in[14];
    const float* v2    = (const float*)d_in[15];
    const float* caw1  = (const float*)d_in[16];
    const float* cab1  = (const float*)d_in[17];
    const float* caw2  = (const float*)d_in[18];
    const float* cab2  = (const float*)d_in[19];
    const float* saw   = (const float*)d_in[20];
    const float* sag   = (const float*)d_in[21];
    const float* sab   = (const float*)d_in[22];
    const float* sam   = (const float*)d_in[23];
    const float* sav   = (const float*)d_in[24];
    const float* sepw  = (const float*)d_in[25];
    const float* sepb  = (const float*)d_in[26];
    const float* g3    = (const float*)d_in[27];
    const float* bb3   = (const float*)d_in[28];
    const float* m3    = (const float*)d_in[29];
    const float* v3    = (const float*)d_in[30];

    cudaFuncSetAttribute(k1_front, cudaFuncAttributeMaxDynamicSharedMemorySize,
                         SMEM_BYTES);

    dim3 grid1(NTILE, BB);
    k1_front<<<grid1, 1024, SMEM_BYTES>>>(x, ahat, w1, b1c, g1, bb1, m1, v1,
                                          gcw, gcb, dww, dwb, g2, bb2, m2, v2);

    dim3 grid2(NTILE2 + 1, BB);
    k2_fused<<<grid2, 256>>>(caw1, cab1, caw2, cab2, saw, sag, sab, sam, sav,
                             sepw, sepb, g3, bb3, m3, v3, (float*)d_out);
}